// round 5
// baseline (speedup 1.0000x reference)
#include <cuda_runtime.h>

// Grid constants (match reference)
#define N_PIX_HI 512
#define NV_HI    256
#define N_PIX_LO 128
#define NV_LO    64
#define PIX_HI_F      0.025f
#define FOV_HALF_HI_F 6.3875f
#define DV_HI_F       3.125f
#define VEL0_HI_F     -404.6875f
#define OUT_ELEMS (NV_LO * N_PIX_LO * N_PIX_LO)   // 1,048,576

__global__ void zero_out_kernel(float4* __restrict__ out, int n4) {
    int i = blockIdx.x * blockDim.x + threadIdx.x;
    if (i < n4) out[i] = make_float4(0.f, 0.f, 0.f, 0.f);
}

// Predicated reduction: single @q RED instruction, no branch.
// A false predicate suppresses the memory access entirely, so the address
// need not be in-bounds when p == 0.
__device__ __forceinline__ void red_add(float* a, float v, int p) {
    asm volatile("{\n\t"
                 ".reg .pred q;\n\t"
                 "setp.ne.s32 q, %2, 0;\n\t"
                 "@q red.global.add.f32 [%0], %1;\n\t"
                 "}"
                 :: "l"(a), "f"(v), "r"(p) : "memory");
}

__device__ __forceinline__ void splat_point(float rr, float dd, float vv, float ff,
                                            float* __restrict__ out) {
    float x = (rr + FOV_HALF_HI_F) / PIX_HI_F;
    float y = (dd + FOV_HALF_HI_F) / PIX_HI_F;
    float v = (vv - VEL0_HI_F)     / DV_HI_F;

    float xf = floorf(x), yf = floorf(y), vf = floorf(v);
    int ix0 = (int)xf, iy0 = (int)yf, iv0 = (int)vf;
    float fx = x - xf, fy = y - yf, fv = v - vf;

    int valid = (ix0 >= 0) & (ix0 < N_PIX_HI - 1) &
                (iy0 >= 0) & (iy0 < N_PIX_HI - 1) &
                (iv0 >= 0) & (iv0 < NV_HI - 1);

    // split flags: hi-res corner i0+1 lands in a different low-res cell
    int sx = (ix0 & 3) == 3;
    int sy = (iy0 & 3) == 3;
    int sv = (iv0 & 3) == 3;

    // merged lo-corner weights: if not split, hi-corner weight folds in -> 1.0
    float wx0 = sx ? (1.0f - fx) : 1.0f;
    float wy0 = sy ? (1.0f - fy) : 1.0f;
    float wv0 = sv ? (1.0f - fv) : 1.0f;

    float f = ff * (1.0f / 64.0f);   // block-mean folded in

    // NO clamping: predicated-off REDs never dereference; true-predicated
    // addresses are in-bounds by construction (split requires i0&3==3).
    int cx0 = ix0 >> 2, cy0 = iy0 >> 2, cv0 = iv0 >> 2;

    float* o = out + ((cv0 * N_PIX_LO + cy0) * N_PIX_LO + cx0);

    float a0 = f * wv0 * wy0;   // (v0,y0)
    float a1 = f * wv0 * fy;    // (v0,y1) - only if sy
    float a2 = f * fv  * wy0;   // (v1,y0) - only if sv
    float a3 = f * fv  * fy;    // (v1,y1) - only if sv&sy

    const int SY = N_PIX_LO;                 // +1 in y
    const int SV = N_PIX_LO * N_PIX_LO;      // +1 in v

    red_add(o,               a0 * wx0, valid);
    red_add(o + 1,           a0 * fx,  valid & sx);
    red_add(o + SY,          a1 * wx0, valid & sy);
    red_add(o + SY + 1,      a1 * fx,  valid & sy & sx);
    red_add(o + SV,          a2 * wx0, valid & sv);
    red_add(o + SV + 1,      a2 * fx,  valid & sv & sx);
    red_add(o + SV + SY,     a3 * wx0, valid & sv & sy);
    red_add(o + SV + SY + 1, a3 * fx,  valid & sv & sy & sx);
}

__global__ void __launch_bounds__(256) splat_kernel(
        const float* __restrict__ ra,
        const float* __restrict__ dec,
        const float* __restrict__ vel,
        const float* __restrict__ flux,
        float* __restrict__ out,
        int n) {
    int i4 = blockIdx.x * blockDim.x + threadIdx.x;
    int base = i4 * 4;
    if (base + 3 < n) {
        float4 r4 = *(const float4*)(ra   + base);
        float4 d4 = *(const float4*)(dec  + base);
        float4 v4 = *(const float4*)(vel  + base);
        float4 f4 = *(const float4*)(flux + base);
        splat_point(r4.x, d4.x, v4.x, f4.x, out);
        splat_point(r4.y, d4.y, v4.y, f4.y, out);
        splat_point(r4.z, d4.z, v4.z, f4.z, out);
        splat_point(r4.w, d4.w, v4.w, f4.w, out);
    } else {
        for (int j = base; j < n; j++)
            splat_point(ra[j], dec[j], vel[j], flux[j], out);
    }
}

extern "C" void kernel_launch(void* const* d_in, const int* in_sizes, int n_in,
                              void* d_out, int out_size) {
    const float* ra   = (const float*)d_in[0];
    const float* dec  = (const float*)d_in[1];
    const float* vel  = (const float*)d_in[2];
    const float* flux = (const float*)d_in[3];
    float* out = (float*)d_out;
    int n = in_sizes[0];

    int nz4 = OUT_ELEMS / 4;
    zero_out_kernel<<<(nz4 + 255) / 256, 256>>>((float4*)out, nz4);

    int nt = (n + 3) / 4;
    splat_kernel<<<(nt + 255) / 256, 256>>>(ra, dec, vel, flux, out, n);
}

// round 7
// speedup vs baseline: 1.4234x; 1.4234x over previous
#include <cuda_runtime.h>

// Grid constants (match reference)
#define N_PIX_HI 512
#define NV_HI    256
#define N_PIX_LO 128
#define NV_LO    64
#define OUT_ELEMS (NV_LO * N_PIX_LO * N_PIX_LO)   // 1,048,576

// Reciprocals (1/0.025f rounds exactly to 40.0f; 1/3.125f ~ 0.32f).
// 1-ulp differences vs div.rn only shift sub-ulp weight between adjacent
// cells at floor boundaries — negligible vs the 1e-3 threshold.
#define INV_PIX_HI_F  40.0f
#define INV_DV_HI_F   0.32f
#define FOV_HALF_HI_F 6.3875f
#define VEL0_HI_F     -404.6875f

__global__ void zero_out_kernel(float4* __restrict__ out, int n4) {
    int i = blockIdx.x * blockDim.x + threadIdx.x;
    if (i < n4) out[i] = make_float4(0.f, 0.f, 0.f, 0.f);
}

// Predicated reduction: single @q RED instruction, no branch.
// False predicate suppresses the access entirely (address may be anything).
__device__ __forceinline__ void red_add(float* a, float v, int p) {
    asm volatile("{\n\t"
                 ".reg .pred q;\n\t"
                 "setp.ne.s32 q, %2, 0;\n\t"
                 "@q red.global.add.f32 [%0], %1;\n\t"
                 "}"
                 :: "l"(a), "f"(v), "r"(p) : "memory");
}

__global__ void __launch_bounds__(256) splat_kernel(
        const float* __restrict__ ra,
        const float* __restrict__ dec,
        const float* __restrict__ vel,
        const float* __restrict__ flux,
        float* __restrict__ out,
        int n) {
    int i = blockIdx.x * blockDim.x + threadIdx.x;
    if (i >= n) return;

    float x = (ra[i]  + FOV_HALF_HI_F) * INV_PIX_HI_F;
    float y = (dec[i] + FOV_HALF_HI_F) * INV_PIX_HI_F;
    float v = (vel[i] - VEL0_HI_F)     * INV_DV_HI_F;

    float xf = floorf(x), yf = floorf(y), vf = floorf(v);
    int ix0 = (int)xf, iy0 = (int)yf, iv0 = (int)vf;
    float fx = x - xf, fy = y - yf, fv = v - vf;

    int valid = (ix0 >= 0) & (ix0 < N_PIX_HI - 1) &
                (iy0 >= 0) & (iy0 < N_PIX_HI - 1) &
                (iv0 >= 0) & (iv0 < NV_HI - 1);

    // split flags: hi-res corner i0+1 lands in a different low-res cell
    int sx = (ix0 & 3) == 3;
    int sy = (iy0 & 3) == 3;
    int sv = (iv0 & 3) == 3;

    // merged lo-corner weights: if not split, hi-corner weight folds to 1.0
    float wx0 = sx ? (1.0f - fx) : 1.0f;
    float wy0 = sy ? (1.0f - fy) : 1.0f;
    float wv0 = sv ? (1.0f - fv) : 1.0f;

    float f = flux[i] * (1.0f / 64.0f);   // block-mean folded in

    int cx0 = ix0 >> 2, cy0 = iy0 >> 2, cv0 = iv0 >> 2;
    float* o = out + ((cv0 * N_PIX_LO + cy0) * N_PIX_LO + cx0);

    float a0 = f * wv0 * wy0;   // (v0,y0)
    float a1 = f * wv0 * fy;    // (v0,y1) - only if sy
    float a2 = f * fv  * wy0;   // (v1,y0) - only if sv
    float a3 = f * fv  * fy;    // (v1,y1) - only if sv&sy

    const int SY = N_PIX_LO;
    const int SV = N_PIX_LO * N_PIX_LO;

    red_add(o,               a0 * wx0, valid);
    red_add(o + 1,           a0 * fx,  valid & sx);
    red_add(o + SY,          a1 * wx0, valid & sy);
    red_add(o + SY + 1,      a1 * fx,  valid & sy & sx);
    red_add(o + SV,          a2 * wx0, valid & sv);
    red_add(o + SV + 1,      a2 * fx,  valid & sv & sx);
    red_add(o + SV + SY,     a3 * wx0, valid & sv & sy);
    red_add(o + SV + SY + 1, a3 * fx,  valid & sv & sy & sx);
}

extern "C" void kernel_launch(void* const* d_in, const int* in_sizes, int n_in,
                              void* d_out, int out_size) {
    const float* ra   = (const float*)d_in[0];
    const float* dec  = (const float*)d_in[1];
    const float* vel  = (const float*)d_in[2];
    const float* flux = (const float*)d_in[3];
    float* out = (float*)d_out;
    int n = in_sizes[0];

    int nz4 = OUT_ELEMS / 4;
    zero_out_kernel<<<(nz4 + 255) / 256, 256>>>((float4*)out, nz4);

    splat_kernel<<<(n + 255) / 256, 256>>>(ra, dec, vel, flux, out, n);
}